// round 1
// baseline (speedup 1.0000x reference)
#include <cuda_runtime.h>
#include <math.h>

// Glm4vMoeTextTopkRouter: fused router GEMM (fp32) + sigmoid + bias top-8 + normalize.
// N_GROUP=1/TOPK_GROUP=1 => group masking is a no-op; selection is plain top-8 of
// sigmoid(logits)+bias, weights = sigmoid(logits) at those indices, normalized.

#define E_EXPERTS 128
#define TOPK 8
#define BM 64          // tokens per block
#define BK 16          // k-slice per tile
#define TM 8           // tokens per thread
#define TN 8           // experts per thread
#define NTHREADS 128   // (BM/TM) * (E/TN) = 8 * 16

__device__ __forceinline__ unsigned long long pack2(float lo, float hi) {
    unsigned long long r;
    asm("mov.b64 %0, {%1, %2};" : "=l"(r) : "f"(lo), "f"(hi));
    return r;
}
__device__ __forceinline__ void unpack2(unsigned long long v, float& lo, float& hi) {
    asm("mov.b64 {%0, %1}, %2;" : "=f"(lo), "=f"(hi) : "l"(v));
}
// Packed fp32x2 FMA (sm_100+): 2 FMAs per instruction, full-rate fma pipe.
__device__ __forceinline__ unsigned long long fma2(unsigned long long a,
                                                   unsigned long long b,
                                                   unsigned long long c) {
    unsigned long long d;
    asm("fma.rn.f32x2 %0, %1, %2, %3;" : "=l"(d) : "l"(a), "l"(b), "l"(c));
    return d;
}

__global__ __launch_bounds__(NTHREADS)
void router_fused_kernel(const float* __restrict__ hidden,
                         const float* __restrict__ weight,
                         const float* __restrict__ bias,
                         float* __restrict__ out,
                         int T, int H)
{
    __shared__ float As[BM][BK + 1];        // [token][k], padded
    __shared__ float Bs[BK][E_EXPERTS];     // [k][expert]
    __shared__ float sc[BM][E_EXPERTS + 1]; // sigmoid scores, padded row=129 -> conflict-free scan
    __shared__ float sbias[E_EXPERTS];

    const int tid = threadIdx.x;
    const int tr  = tid >> 4;   // 0..7  token row group
    const int tc  = tid & 15;   // 0..15 expert col group
    const int m0  = blockIdx.x * BM;

    sbias[tid] = bias[tid];     // NTHREADS == E_EXPERTS

    // accumulators: expert-pairs packed as f32x2
    unsigned long long acc2[TM][TN / 2];
#pragma unroll
    for (int i = 0; i < TM; i++)
#pragma unroll
        for (int j = 0; j < TN / 2; j++) acc2[i][j] = 0ULL;

    // A staging: thread -> token (tid/2), k-offset (tid%2)*8 : 2x float4
    const int a_tok = tid >> 1;
    const int a_k   = (tid & 1) * 8;
    int a_row = m0 + a_tok; if (a_row >= T) a_row = T - 1;   // defensive clamp
    const float* aBase = hidden + (size_t)a_row * H + a_k;
    // B staging: thread -> expert row tid : 4x float4 (16 k-values)
    const float* bBase = weight + (size_t)tid * H;

    float4 aReg[2], bReg[4];
    const int NT = H / BK;

    // prologue: stage tile 0
    aReg[0] = *(const float4*)(aBase + 0);
    aReg[1] = *(const float4*)(aBase + 4);
#pragma unroll
    for (int q = 0; q < 4; q++) bReg[q] = *(const float4*)(bBase + q * 4);

    for (int t = 0; t < NT; ++t) {
        // commit staged regs to smem (A transposed-free [tok][k]; B transposed [k][e])
#pragma unroll
        for (int v = 0; v < 2; v++) {
            As[a_tok][a_k + 4 * v + 0] = ((float*)&aReg[v])[0];
            As[a_tok][a_k + 4 * v + 1] = ((float*)&aReg[v])[1];
            As[a_tok][a_k + 4 * v + 2] = ((float*)&aReg[v])[2];
            As[a_tok][a_k + 4 * v + 3] = ((float*)&aReg[v])[3];
        }
#pragma unroll
        for (int q = 0; q < 4; q++) {
            Bs[q * 4 + 0][tid] = ((float*)&bReg[q])[0];
            Bs[q * 4 + 1][tid] = ((float*)&bReg[q])[1];
            Bs[q * 4 + 2][tid] = ((float*)&bReg[q])[2];
            Bs[q * 4 + 3][tid] = ((float*)&bReg[q])[3];
        }
        __syncthreads();

        // prefetch next tile into regs (LDG latency overlaps compute below)
        if (t + 1 < NT) {
            const float* ap = aBase + (size_t)(t + 1) * BK;
            aReg[0] = *(const float4*)(ap);
            aReg[1] = *(const float4*)(ap + 4);
            const float* bp = bBase + (size_t)(t + 1) * BK;
#pragma unroll
            for (int q = 0; q < 4; q++) bReg[q] = *(const float4*)(bp + q * 4);
        }

        // mainloop: 16 k-steps, 32 FFMA2 each
#pragma unroll
        for (int k = 0; k < BK; k++) {
            const ulonglong2* bp2 = (const ulonglong2*)(&Bs[k][tc * TN]);
            ulonglong2 b01 = bp2[0];
            ulonglong2 b23 = bp2[1];
            unsigned long long bb0 = b01.x, bb1 = b01.y, bb2 = b23.x, bb3 = b23.y;
#pragma unroll
            for (int i = 0; i < TM; i++) {
                float a = As[tr * TM + i][k];
                unsigned long long aa = pack2(a, a);
                acc2[i][0] = fma2(aa, bb0, acc2[i][0]);
                acc2[i][1] = fma2(aa, bb1, acc2[i][1]);
                acc2[i][2] = fma2(aa, bb2, acc2[i][2]);
                acc2[i][3] = fma2(aa, bb3, acc2[i][3]);
            }
        }
        __syncthreads();
    }

    // epilogue: sigmoid -> smem scoreboard
#pragma unroll
    for (int i = 0; i < TM; i++) {
#pragma unroll
        for (int j = 0; j < TN / 2; j++) {
            float lo, hi;
            unpack2(acc2[i][j], lo, hi);
            int row = tr * TM + i;
            int col = tc * TN + 2 * j;
            sc[row][col]     = 1.0f / (1.0f + expf(-lo));
            sc[row][col + 1] = 1.0f / (1.0f + expf(-hi));
        }
    }
    __syncthreads();

    // per-token top-8 (threads 0..63). strict '>' keeps lowest index on ties,
    // matching jax.lax.top_k ordering.
    if (tid < BM && (m0 + tid) < T) {
        const int gtok = m0 + tid;
        float w[TOPK];
        int   idx[TOPK];
        float s = 0.0f;
#pragma unroll
        for (int p = 0; p < TOPK; p++) {
            float m = -1e30f;
            int mi = 0;
#pragma unroll 16
            for (int e = 0; e < E_EXPERTS; e++) {
                float v = sc[tid][e] + sbias[e];   // selection score = sigmoid + bias
                if (v > m) { m = v; mi = e; }
            }
            idx[p] = mi;
            w[p]   = sc[tid][mi];                  // weight = sigmoid (no bias)
            sc[tid][mi] = -3e30f;                  // exclude from later passes
            s += w[p];
        }
        const float inv = 1.0f / (s + 1e-20f);
        float* oi = out + (size_t)gtok * TOPK;
        float* ow = out + (size_t)T * TOPK + (size_t)gtok * TOPK;
#pragma unroll
        for (int p = 0; p < TOPK; p++) {
            oi[p] = (float)idx[p];
            ow[p] = w[p] * inv;
        }
    }
}

extern "C" void kernel_launch(void* const* d_in, const int* in_sizes, int n_in,
                              void* d_out, int out_size)
{
    const float* hidden = (const float*)d_in[0];
    const float* weight = (const float*)d_in[1];
    const float* bias   = (const float*)d_in[2];

    const int H = in_sizes[1] / E_EXPERTS;     // 4096
    const int T = in_sizes[0] / H;             // 32768

    const int grid = (T + BM - 1) / BM;        // 512 blocks
    router_fused_kernel<<<grid, NTHREADS>>>(hidden, weight, bias, (float*)d_out, T, H);
}

// round 5
// speedup vs baseline: 2.6048x; 2.6048x over previous
#include <cuda_runtime.h>
#include <cuda_fp16.h>
#include <math.h>
#include <stdint.h>

// Glm4vMoeTextTopkRouter: tensor-core router GEMM (baseline mma.sync, fp16 split precision
// with scaled residuals) + periodic software flush of TC accumulators (fp32-exact class)
// + fused sigmoid + bias top-8 + normalize.
//   a = a_hi + a_lo'/2048 ; b = b_hi + b_lo'/2048   (a_lo' = fp16((a-a_hi)*2048), normalized)
//   logit = HH + (HL + LH)/2048, each accumulated in TC fp32 but flushed to a software
//   fp32 sum every 4 chunks to kill the TC C-add truncation bias.

#define HD 4096
#define NE 128
#define TOPK 8
#define BM 64                // tokens per CTA
#define KC 64                // k per chunk
#define NCH (HD / KC)        // 64
#define NT 256               // 8 warps

#define OFF_BIAS  0
#define OFF_STAGE 512
#define A_MAT 8192           // 64 rows x 128B
#define B_MAT 16384          // 128 rows x 128B
#define STG (2 * A_MAT + 2 * B_MAT)       // 49152: A_hi | A_lo | B_hi | B_lo
#define SMEM_TOTAL (OFF_STAGE + 2 * STG)  // 98816

#define LO_SCALE 2048.0f
#define LO_INV   (1.0f / 2048.0f)

#define SW128(o) ((uint32_t)(o) ^ ((((uint32_t)(o)) >> 3) & 0x70))

__device__ __forceinline__ uint32_t smem_u32(const void* p) {
    uint32_t a;
    asm("{ .reg .u64 t; cvta.to.shared.u64 t, %1; cvt.u32.u64 %0, t; }" : "=r"(a) : "l"(p));
    return a;
}

__device__ __forceinline__ void ldsm_x4(uint32_t addr, uint32_t& r0, uint32_t& r1,
                                        uint32_t& r2, uint32_t& r3) {
    asm volatile("ldmatrix.sync.aligned.m8n8.x4.shared.b16 {%0,%1,%2,%3}, [%4];"
                 : "=r"(r0), "=r"(r1), "=r"(r2), "=r"(r3) : "r"(addr));
}

__device__ __forceinline__ void mma16816(float* c, const uint32_t* a, uint32_t b0, uint32_t b1) {
    asm volatile("mma.sync.aligned.m16n8k16.row.col.f32.f16.f16.f32 "
                 "{%0,%1,%2,%3}, {%4,%5,%6,%7}, {%8,%9}, {%0,%1,%2,%3};"
                 : "+f"(c[0]), "+f"(c[1]), "+f"(c[2]), "+f"(c[3])
                 : "r"(a[0]), "r"(a[1]), "r"(a[2]), "r"(a[3]), "r"(b0), "r"(b1));
}

__device__ __forceinline__ uint32_t h2u(half2 h) { return *reinterpret_cast<uint32_t*>(&h); }

__device__ __forceinline__ void store_split(char* hi_p, char* lo_p, float4 v) {
    half2 h0 = __floats2half2_rn(v.x, v.y);
    half2 h1 = __floats2half2_rn(v.z, v.w);
    float2 f0 = __half22float2(h0);
    float2 f1 = __half22float2(h1);
    half2 l0 = __floats2half2_rn((v.x - f0.x) * LO_SCALE, (v.y - f0.y) * LO_SCALE);
    half2 l1 = __floats2half2_rn((v.z - f1.x) * LO_SCALE, (v.w - f1.y) * LO_SCALE);
    *(uint2*)hi_p = make_uint2(h2u(h0), h2u(h1));
    *(uint2*)lo_p = make_uint2(h2u(l0), h2u(l1));
}

// verified ldmatrix address maps (128B pitch, SW128)
__device__ __forceinline__ uint32_t a_addr(uint32_t base, int l, int mb, int kb) {
    int row = mb + (l & 7) + ((l >> 3) & 1) * 8;
    int colb = (kb + ((l >> 4) << 3)) * 2;
    return base + SW128(row * 128 + colb);
}
__device__ __forceinline__ uint32_t b_addr(uint32_t base, int l, int nb, int kb) {
    int row = nb + (l & 7) + ((l >> 4) << 3);
    int colb = (kb + (((l >> 3) & 1) << 3)) * 2;
    return base + SW128(row * 128 + colb);
}

__global__ __launch_bounds__(NT, 1)
void router_mma_kernel(const float* __restrict__ hidden,
                       const float* __restrict__ weight,
                       const float* __restrict__ bias,
                       float* __restrict__ out, int T)
{
    extern __shared__ char smem[];
    const uint32_t sbase = smem_u32(smem);
    const int tid = threadIdx.x;
    const int wid = tid >> 5, lid = tid & 31;
    const int m0 = blockIdx.x * BM;

    if (tid < NE) ((float*)(smem + OFF_BIAS))[tid] = bias[tid];

    const int arow = tid >> 4;   // 0..15
    const int c4   = tid & 15;   // float4 within KC=64
    const float* aBase = hidden + (size_t)(m0 + arow) * HD + c4 * 4;
    const float* bBase = weight + (size_t)arow * HD + c4 * 4;

    // warp tile: m16 x n64 (4 m-groups x 2 n-groups)
    const int mb = (wid >> 1) * 16;
    const int nb = (wid & 1) * 64;

    float acc[8][4], corA[8][4], corB[8][4], sum[8][4];
#pragma unroll
    for (int j = 0; j < 8; j++)
#pragma unroll
        for (int q = 0; q < 4; q++) {
            acc[j][q] = 0.0f; corA[j][q] = 0.0f; corB[j][q] = 0.0f; sum[j][q] = 0.0f;
        }

    float4 va[4], vb[8];
#pragma unroll
    for (int i = 0; i < 4; i++) va[i] = *(const float4*)(aBase + (size_t)(i * 16) * HD);
#pragma unroll
    for (int i = 0; i < 8; i++) vb[i] = *(const float4*)(bBase + (size_t)(i * 16) * HD);

    for (int c = 0; c < NCH; ++c) {
        char* stg = smem + OFF_STAGE + (c & 1) * STG;
#pragma unroll
        for (int i = 0; i < 4; i++) {   // A: 64 rows
            uint32_t off = SW128((uint32_t)((i * 16 + arow) * 128 + c4 * 8));
            store_split(stg + off, stg + A_MAT + off, va[i]);
        }
#pragma unroll
        for (int i = 0; i < 8; i++) {   // B: 128 rows
            uint32_t off = SW128((uint32_t)((i * 16 + arow) * 128 + c4 * 8));
            store_split(stg + 2 * A_MAT + off, stg + 2 * A_MAT + B_MAT + off, vb[i]);
        }
        if (c + 1 < NCH) {
            const float* ap = aBase + (size_t)(c + 1) * KC;
            const float* bp = bBase + (size_t)(c + 1) * KC;
#pragma unroll
            for (int i = 0; i < 4; i++) va[i] = *(const float4*)(ap + (size_t)(i * 16) * HD);
#pragma unroll
            for (int i = 0; i < 8; i++) vb[i] = *(const float4*)(bp + (size_t)(i * 16) * HD);
        }
        __syncthreads();   // orders STS->LDSM; buffer-reuse safety via next iter's bar

        const uint32_t sA_hi = sbase + OFF_STAGE + (c & 1) * STG;
        const uint32_t sA_lo = sA_hi + A_MAT;
        const uint32_t sB_hi = sA_hi + 2 * A_MAT;
        const uint32_t sB_lo = sB_hi + B_MAT;

#pragma unroll
        for (int ks = 0; ks < 4; ks++) {
            const int kb = ks * 16;
            uint32_t ah[4], al[4];
            ldsm_x4(a_addr(sA_hi, lid, mb, kb), ah[0], ah[1], ah[2], ah[3]);
            ldsm_x4(a_addr(sA_lo, lid, mb, kb), al[0], al[1], al[2], al[3]);
#pragma unroll
            for (int ng = 0; ng < 4; ng++) {
                uint32_t bh0, bh1, bh2, bh3, bl0, bl1, bl2, bl3;
                ldsm_x4(b_addr(sB_hi, lid, nb + ng * 16, kb), bh0, bh1, bh2, bh3);
                ldsm_x4(b_addr(sB_lo, lid, nb + ng * 16, kb), bl0, bl1, bl2, bl3);
                // all 6 MMAs hit distinct accumulator regs -> no RAW chaining within ng
                mma16816(acc [ng * 2 + 0], ah, bh0, bh1);   // hi*hi
                mma16816(acc [ng * 2 + 1], ah, bh2, bh3);
                mma16816(corA[ng * 2 + 0], ah, bl0, bl1);   // hi*lo'
                mma16816(corA[ng * 2 + 1], ah, bl2, bl3);
                mma16816(corB[ng * 2 + 0], al, bh0, bh1);   // lo'*hi
                mma16816(corB[ng * 2 + 1], al, bh2, bh3);
            }
        }

        // flush TC accumulators into software fp32 sum every 4 chunks (kills TC C-add bias)
        if ((c & 3) == 3) {
#pragma unroll
            for (int j = 0; j < 8; j++)
#pragma unroll
                for (int q = 0; q < 4; q++) {
                    float s = sum[j][q] + acc[j][q];
                    s = fmaf(corA[j][q], LO_INV, s);
                    s = fmaf(corB[j][q], LO_INV, s);
                    sum[j][q] = s;
                    acc[j][q] = 0.0f; corA[j][q] = 0.0f; corB[j][q] = 0.0f;
                }
        }
    }

    __syncthreads();   // all LDSM reads done before scoreboard overlays stage smem

    // epilogue: sigmoid(sum) -> scoreboard [row][129]
    float* sc = (float*)(smem + OFF_STAGE);
    {
        const int r0 = lid >> 2;
        const int cc = (lid & 3) * 2;
#pragma unroll
        for (int ni = 0; ni < 8; ni++) {
            const int col = nb + ni * 8 + cc;
#pragma unroll
            for (int q = 0; q < 4; q++) {
                const int row = mb + r0 + (q >> 1) * 8;
                sc[row * 129 + col + (q & 1)] = 1.0f / (1.0f + expf(-sum[ni][q]));
            }
        }
    }
    __syncthreads();

    // top-8 per token (threads 0..63); strict '>' => lowest-index ties like lax.top_k
    if (tid < BM) {
        const int gtok = m0 + tid;
        float* row = sc + tid * 129;
        const float* sb = (const float*)(smem + OFF_BIAS);
        float w[TOPK]; int idx[TOPK]; float ssum = 0.0f;
#pragma unroll
        for (int p = 0; p < TOPK; p++) {
            float mx = -1e30f; int mi = 0;
#pragma unroll 16
            for (int e = 0; e < NE; e++) {
                float v = row[e] + sb[e];
                if (v > mx) { mx = v; mi = e; }
            }
            idx[p] = mi;
            w[p] = row[mi];
            row[mi] = -3e30f;
            ssum += w[p];
        }
        const float inv = 1.0f / (ssum + 1e-20f);
        float* oi = out + (size_t)gtok * TOPK;
        float* ow = out + (size_t)T * TOPK + (size_t)gtok * TOPK;
#pragma unroll
        for (int p = 0; p < TOPK; p++) {
            oi[p] = (float)idx[p];
            ow[p] = w[p] * inv;
        }
    }
}

extern "C" void kernel_launch(void* const* d_in, const int* in_sizes, int n_in,
                              void* d_out, int out_size)
{
    const float* hidden = (const float*)d_in[0];
    const float* weight = (const float*)d_in[1];
    const float* bias   = (const float*)d_in[2];
    const int T = in_sizes[0] / HD;   // 32768

    cudaFuncSetAttribute(router_mma_kernel,
                         cudaFuncAttributeMaxDynamicSharedMemorySize, SMEM_TOTAL);
    router_mma_kernel<<<T / BM, NT, SMEM_TOTAL>>>(hidden, weight, bias, (float*)d_out, T);
}